// round 6
// baseline (speedup 1.0000x reference)
#include <cuda_runtime.h>
#include <cuda_bf16.h>
#include <math.h>
#include <stdint.h>

#define VV   32000
#define EE   300
#define HH   256
#define G4   1024
#define H2   512
#define H8   2048
#define BB   64
#define LQ   64
#define LC   512

__device__ float g_qemb[(size_t)BB * LQ * EE];
__device__ float g_cemb[(size_t)BB * LC * EE];
__device__ float g_xw  [(size_t)2 * BB * LC * G4];
__device__ float g_qout[(size_t)BB * LQ * H2];
__device__ float g_cout[(size_t)BB * LC * H2];
__device__ float g_S   [(size_t)BB * LC * LQ];
__device__ float g_smax[(size_t)BB * LC];
__device__ float g_batt[(size_t)BB * LC];
__device__ float g_cw  [(size_t)BB * LC];
__device__ float g_qw  [(size_t)BB * LQ];
__device__ float g_c2q [(size_t)BB * LC * H2];
__device__ float g_q2c [(size_t)BB * H2];
__device__ float g_G   [(size_t)BB * LC * H8];
__device__ float g_M   [(size_t)BB * LC * H2];

__device__ __forceinline__ float sigmoidf_(float x) { return 1.f / (1.f + expf(-x)); }

__device__ __forceinline__ uint32_t f2tf32(float x)
{
    uint32_t r;
    asm("cvt.rna.tf32.f32 %0, %1;" : "=r"(r) : "f"(x));
    return r;
}

__device__ __forceinline__ uint32_t smem_u32(const void* p)
{
    uint32_t a;
    asm("{ .reg .u64 t; cvta.to.shared.u64 t, %1; cvt.u32.u64 %0, t; }" : "=r"(a) : "l"(p));
    return a;
}

// ---------------------------------------------------------------------------
__global__ void gather_emb(const int* __restrict__ tok, const float* __restrict__ emb,
                           float* __restrict__ out, int total)
{
    int i = blockIdx.x * blockDim.x + threadIdx.x;
    if (i >= total) return;
    int row = i / EE;
    int e   = i - row * EE;
    out[i] = emb[(size_t)tok[row] * EE + e];
}

// ---------------------------------------------------------------------------
// tf32 mma.sync GEMM  C = A[M,K] * B[N,K]^T + bias  (unchanged, measured 67TF/s)
// ---------------------------------------------------------------------------
#define SROW 36
#define STILE (128 * SROW)

__device__ __forceinline__ void gtile_load(const float* __restrict__ P, int row_base,
                                           int K, int k0, int tid, float4* r)
{
#pragma unroll
    for (int i = 0; i < 4; ++i) {
        int idx = tid + i * 256;
        int row = idx >> 3, c4 = idx & 7;
        int kcol = k0 + c4 * 4;
        float4 v = make_float4(0.f, 0.f, 0.f, 0.f);
        if (kcol + 4 <= K)
            v = *(const float4*)&P[(size_t)(row_base + row) * K + kcol];
        r[i] = v;
    }
}

__device__ __forceinline__ void stile_store(float* Sb, int tid, const float4* r)
{
#pragma unroll
    for (int i = 0; i < 4; ++i) {
        int idx = tid + i * 256;
        int row = idx >> 3, c4 = idx & 7;
        float* p = Sb + row * SROW + c4 * 4;
        p[0] = __uint_as_float(f2tf32(r[i].x));
        p[1] = __uint_as_float(f2tf32(r[i].y));
        p[2] = __uint_as_float(f2tf32(r[i].z));
        p[3] = __uint_as_float(f2tf32(r[i].w));
    }
}

__global__ void __launch_bounds__(256)
gemm_tf32(const float* __restrict__ A, const float* __restrict__ B,
          const float* __restrict__ bias, float* __restrict__ C,
          int M, int N, int K)
{
    extern __shared__ float sh[];
    float* Asm = sh;
    float* Bsm = sh + 2 * STILE;

    const int tid  = threadIdx.x;
    const int lane = tid & 31;
    const int warp = tid >> 5;
    const int g = lane >> 2, t = lane & 3;
    const int m0 = (warp & 3) * 32;
    const int n0 = (warp >> 2) * 64;
    const int bm = blockIdx.y * 128;
    const int bn = blockIdx.x * 128;

    float acc[2][8][4];
#pragma unroll
    for (int mi = 0; mi < 2; ++mi)
#pragma unroll
        for (int ni = 0; ni < 8; ++ni)
#pragma unroll
            for (int k = 0; k < 4; ++k) acc[mi][ni][k] = 0.f;

    const int nk = (K + 31) >> 5;
    float4 pa[4], pb[4];

    gtile_load(A, bm, K, 0, tid, pa);
    gtile_load(B, bn, K, 0, tid, pb);
    stile_store(Asm, tid, pa);
    stile_store(Bsm, tid, pb);
    __syncthreads();

    int buf = 0;
    for (int kt = 0; kt < nk; ++kt) {
        if (kt + 1 < nk) {
            gtile_load(A, bm, K, (kt + 1) * 32, tid, pa);
            gtile_load(B, bn, K, (kt + 1) * 32, tid, pb);
        }
        const float* Ab = Asm + buf * STILE;
        const float* Bb = Bsm + buf * STILE;
#pragma unroll
        for (int kk = 0; kk < 32; kk += 8) {
            uint32_t af[2][4];
#pragma unroll
            for (int mi = 0; mi < 2; ++mi) {
                const float* ap = Ab + (m0 + mi * 16) * SROW + kk;
                af[mi][0] = __float_as_uint(ap[g * SROW + t]);
                af[mi][1] = __float_as_uint(ap[(g + 8) * SROW + t]);
                af[mi][2] = __float_as_uint(ap[g * SROW + t + 4]);
                af[mi][3] = __float_as_uint(ap[(g + 8) * SROW + t + 4]);
            }
            uint32_t bf[8][2];
#pragma unroll
            for (int ni = 0; ni < 8; ++ni) {
                const float* bp = Bb + (n0 + ni * 8) * SROW + kk;
                bf[ni][0] = __float_as_uint(bp[g * SROW + t]);
                bf[ni][1] = __float_as_uint(bp[g * SROW + t + 4]);
            }
#pragma unroll
            for (int mi = 0; mi < 2; ++mi)
#pragma unroll
                for (int ni = 0; ni < 8; ++ni)
                    asm volatile(
                        "mma.sync.aligned.m16n8k8.row.col.f32.tf32.tf32.f32 "
                        "{%0,%1,%2,%3}, {%4,%5,%6,%7}, {%8,%9}, {%0,%1,%2,%3};\n"
                        : "+f"(acc[mi][ni][0]), "+f"(acc[mi][ni][1]),
                          "+f"(acc[mi][ni][2]), "+f"(acc[mi][ni][3])
                        : "r"(af[mi][0]), "r"(af[mi][1]), "r"(af[mi][2]), "r"(af[mi][3]),
                          "r"(bf[ni][0]), "r"(bf[ni][1]));
        }
        if (kt + 1 < nk) {
            __syncthreads();
            stile_store(Asm + (buf ^ 1) * STILE, tid, pa);
            stile_store(Bsm + (buf ^ 1) * STILE, tid, pb);
            __syncthreads();
            buf ^= 1;
        }
    }
#pragma unroll
    for (int mi = 0; mi < 2; ++mi) {
#pragma unroll
        for (int ni = 0; ni < 8; ++ni) {
            int row0 = bm + m0 + mi * 16 + g;
            int col  = bn + n0 + ni * 8 + t * 2;
            float2 bv = make_float2(0.f, 0.f);
            if (bias) bv = *(const float2*)&bias[col];
            *(float2*)&C[(size_t)row0 * N + col] =
                make_float2(acc[mi][ni][0] + bv.x, acc[mi][ni][1] + bv.y);
            *(float2*)&C[(size_t)(row0 + 8) * N + col] =
                make_float2(acc[mi][ni][2] + bv.x, acc[mi][ni][3] + bv.y);
        }
    }
}

// ---------------------------------------------------------------------------
// Cluster BiLSTM scan: 128 CTAs = 2 dir x 8 batch-groups x cluster(8 hidden
// partitions). Whh slice (128x256) in smem; h double-buffered in smem,
// exchanged via DSMEM multicast stores; one barrier.cluster per step.
// Thread (rg=tid>>3, b=tid&7) owns unit part*32+rg of batch bg*8+b.
// ---------------------------------------------------------------------------
#define LW 260                         // padded row stride (bank-conflict-free)
#define LS_H (128 * LW)
#define LS_X (LS_H + 2 * 8 * LW)
#define LSTM_SMEM ((LS_X + 1024) * 4)  // 153,856 B

__global__ void __launch_bounds__(256) __cluster_dims__(8, 1, 1)
lstm_scan(const float* __restrict__ xW, const float* __restrict__ Whh,
          float* __restrict__ out, int T)
{
    extern __shared__ float sh[];
    float* w_sh = sh;
    float* h_sh = sh + LS_H;
    float* xs   = sh + LS_X;

    const int tid = threadIdx.x;
    const int rg  = tid >> 3;
    const int b   = tid & 7;
    uint32_t rank;
    asm("mov.u32 %0, %%cluster_ctarank;" : "=r"(rank));
    const int cl   = blockIdx.x >> 3;
    const int dir  = cl >> 3;
    const int bg   = cl & 7;
    const int part = (int)rank;
    const int unit = part * 32 + rg;

    // load this partition's 128 Whh rows (2 threads per row)
    const float* WhhD = Whh + (size_t)dir * G4 * HH;
    {
        int r = tid >> 1;
        int gg = r >> 5, j = r & 31, half = (tid & 1) * 128;
        const float* src = &WhhD[(size_t)(gg * HH + part * 32 + j) * HH + half];
        float* dst = &w_sh[r * LW + half];
#pragma unroll
        for (int k = 0; k < 128; k += 4)
            *(float4*)&dst[k] = *(const float4*)&src[k];
    }
    for (int i = tid; i < 2 * 8 * LW; i += 256) h_sh[i] = 0.f;
    __syncthreads();

    uint32_t hbase = smem_u32(h_sh);
    uint32_t peer[8];
#pragma unroll
    for (int r = 0; r < 8; ++r)
        asm("mapa.shared::cluster.u32 %0, %1, %2;" : "=r"(peer[r]) : "r"(hbase), "r"(r));

    asm volatile("barrier.cluster.arrive.aligned;" ::: "memory");
    asm volatile("barrier.cluster.wait.aligned;" ::: "memory");

    const float* xWD = xW + (size_t)dir * BB * T * G4;
    const float* w0 = &w_sh[(0 * 32 + rg) * LW];
    const float* w1 = &w_sh[(1 * 32 + rg) * LW];
    const float* w2 = &w_sh[(2 * 32 + rg) * LW];
    const float* w3 = &w_sh[(3 * 32 + rg) * LW];
    float creg = 0.f;
    int buf = 0;

    for (int s = 0; s < T; ++s) {
        const int tt = dir ? (T - 1 - s) : s;
        {   // stage xW tile (coalesced): 8 batches x 4 gates x 32 units
            int lb = tid >> 5, gg = (tid >> 3) & 3, qd = tid & 7;
            float4 v = *(const float4*)&xWD[((size_t)(bg * 8 + lb) * T + tt) * G4
                                            + gg * HH + part * 32 + qd * 4];
            *(float4*)&xs[(lb * 4 + gg) * 32 + qd * 4] = v;
        }
        float d0 = 0.f, d1 = 0.f, d2 = 0.f, d3 = 0.f;
        if (s > 0) {
            const float* hb = &h_sh[(buf * 8 + b) * LW];
#pragma unroll 8
            for (int k = 0; k < HH; k += 4) {
                float4 h4 = *(const float4*)&hb[k];
                float4 v0 = *(const float4*)&w0[k];
                float4 v1 = *(const float4*)&w1[k];
                float4 v2 = *(const float4*)&w2[k];
                float4 v3 = *(const float4*)&w3[k];
                d0 += v0.x * h4.x; d0 += v0.y * h4.y; d0 += v0.z * h4.z; d0 += v0.w * h4.w;
                d1 += v1.x * h4.x; d1 += v1.y * h4.y; d1 += v1.z * h4.z; d1 += v1.w * h4.w;
                d2 += v2.x * h4.x; d2 += v2.y * h4.y; d2 += v2.z * h4.z; d2 += v2.w * h4.w;
                d3 += v3.x * h4.x; d3 += v3.y * h4.y; d3 += v3.z * h4.z; d3 += v3.w * h4.w;
            }
        }
        __syncthreads();   // xs ready (also fences prior h reads before rewrites)

        float ig = sigmoidf_(d0 + xs[(b * 4 + 0) * 32 + rg]);
        float fg = sigmoidf_(d1 + xs[(b * 4 + 1) * 32 + rg]);
        float gg = tanhf(d2 + xs[(b * 4 + 2) * 32 + rg]);
        float og = sigmoidf_(d3 + xs[(b * 4 + 3) * 32 + rg]);
        creg = fg * creg + ig * gg;
        float hh = og * tanhf(creg);

        // broadcast h to all 8 cluster CTAs (double-buffered slot)
        uint32_t off = (uint32_t)((((buf ^ 1) * 8 + b) * LW + unit) * 4);
#pragma unroll
        for (int r = 0; r < 8; ++r)
            asm volatile("st.shared::cluster.f32 [%0], %1;"
                         :: "r"(peer[r] + off), "f"(hh) : "memory");

        asm volatile("barrier.cluster.arrive.aligned;" ::: "memory");
        asm volatile("barrier.cluster.wait.aligned;" ::: "memory");

        // coalesced out store of this partition's units from synced buffer
        if (tid < 64) {
            int ob = tid >> 3, oq = tid & 7;
            float4 v = *(const float4*)&h_sh[((buf ^ 1) * 8 + ob) * LW + part * 32 + oq * 4];
            *(float4*)&out[((size_t)(bg * 8 + ob) * T + tt) * H2
                           + dir * HH + part * 32 + oq * 4] = v;
        }
        buf ^= 1;
    }
}

// ---------------------------------------------------------------------------
__global__ void rowdot(const float* __restrict__ A, const float* __restrict__ w,
                       const float* __restrict__ bias, float* __restrict__ out, int rows)
{
    int gw = (blockIdx.x * blockDim.x + threadIdx.x) >> 5;
    int lane = threadIdx.x & 31;
    if (gw >= rows) return;
    const float* row = A + (size_t)gw * H2;
    float s = 0.f;
#pragma unroll
    for (int i = 0; i < 16; ++i) s += row[lane + i * 32] * w[lane + i * 32];
#pragma unroll
    for (int off = 16; off; off >>= 1) s += __shfl_xor_sync(0xffffffffu, s, off);
    if (lane == 0) out[gw] = s + (bias ? bias[0] : 0.f);
}

__global__ void __launch_bounds__(256)
attn_S(const float* __restrict__ c_out, const float* __restrict__ q_out,
       const float* __restrict__ sim_w, const float* __restrict__ sim_b,
       const float* __restrict__ cw, const float* __restrict__ qw,
       float* __restrict__ S)
{
    __shared__ float As[16][68];
    __shared__ float Bs[16][68];
    const int b = blockIdx.y, cc0 = blockIdx.x * 64;
    const float* A  = c_out + ((size_t)b * LC + cc0) * H2;
    const float* Bq = q_out + (size_t)b * LQ * H2;
    const float* wcq = sim_w + 2 * H2;
    const int tid = threadIdx.x;
    const int lr = tid >> 2, lk4 = (tid & 3) * 4;
    const int tx = tid & 15, ty = tid >> 4;
    float acc[4][4];
#pragma unroll
    for (int i = 0; i < 4; ++i)
#pragma unroll
        for (int j = 0; j < 4; ++j) acc[i][j] = 0.f;

    for (int k0 = 0; k0 < H2; k0 += 16) {
        float4 va = *(const float4*)&A[(size_t)lr * H2 + k0 + lk4];
        float4 wv = *(const float4*)&wcq[k0 + lk4];
        As[lk4 + 0][lr] = va.x * wv.x;
        As[lk4 + 1][lr] = va.y * wv.y;
        As[lk4 + 2][lr] = va.z * wv.z;
        As[lk4 + 3][lr] = va.w * wv.w;
        float4 vb = *(const float4*)&Bq[(size_t)lr * H2 + k0 + lk4];
        Bs[lk4 + 0][lr] = vb.x;
        Bs[lk4 + 1][lr] = vb.y;
        Bs[lk4 + 2][lr] = vb.z;
        Bs[lk4 + 3][lr] = vb.w;
        __syncthreads();
#pragma unroll
        for (int k = 0; k < 16; ++k) {
            float4 av = *(const float4*)&As[k][ty * 4];
            float4 bv = *(const float4*)&Bs[k][tx * 4];
            float am[4] = {av.x, av.y, av.z, av.w};
            float bn[4] = {bv.x, bv.y, bv.z, bv.w};
#pragma unroll
            for (int i = 0; i < 4; ++i)
#pragma unroll
                for (int j = 0; j < 4; ++j) acc[i][j] += am[i] * bn[j];
        }
        __syncthreads();
    }
    float sb = sim_b[0];
#pragma unroll
    for (int i = 0; i < 4; ++i) {
        int cc = cc0 + ty * 4 + i;
        float cwv = cw[b * LC + cc];
#pragma unroll
        for (int j = 0; j < 4; ++j) {
            int qq = tx * 4 + j;
            S[((size_t)b * LC + cc) * LQ + qq] = acc[i][j] + cwv + qw[b * LQ + qq] + sb;
        }
    }
}

__global__ void softmax64(float* __restrict__ S, float* __restrict__ smax, int rows)
{
    int gw = (blockIdx.x * blockDim.x + threadIdx.x) >> 5;
    int lane = threadIdx.x & 31;
    if (gw >= rows) return;
    float* row = S + (size_t)gw * LQ;
    float v0 = row[lane], v1 = row[lane + 32];
    float m = fmaxf(v0, v1);
#pragma unroll
    for (int off = 16; off; off >>= 1) m = fmaxf(m, __shfl_xor_sync(0xffffffffu, m, off));
    float e0 = expf(v0 - m), e1 = expf(v1 - m);
    float s = e0 + e1;
#pragma unroll
    for (int off = 16; off; off >>= 1) s += __shfl_xor_sync(0xffffffffu, s, off);
    float inv = 1.f / s;
    row[lane] = e0 * inv;
    row[lane + 32] = e1 * inv;
    if (lane == 0) smax[gw] = m;
}

__global__ void softmax512(const float* __restrict__ in, float* __restrict__ outv)
{
    __shared__ float red[16];
    int b = blockIdx.x, tid = threadIdx.x;
    float v = in[(size_t)b * LC + tid];
    float m = v;
#pragma unroll
    for (int off = 16; off; off >>= 1) m = fmaxf(m, __shfl_xor_sync(0xffffffffu, m, off));
    if ((tid & 31) == 0) red[tid >> 5] = m;
    __syncthreads();
    if (tid == 0) {
        float x = red[0];
        for (int i = 1; i < 16; ++i) x = fmaxf(x, red[i]);
        red[0] = x;
    }
    __syncthreads();
    m = red[0];
    __syncthreads();
    float e = expf(v - m);
    float s = e;
#pragma unroll
    for (int off = 16; off; off >>= 1) s += __shfl_xor_sync(0xffffffffu, s, off);
    if ((tid & 31) == 0) red[tid >> 5] = s;
    __syncthreads();
    if (tid == 0) {
        float x = 0.f;
        for (int i = 0; i < 16; ++i) x += red[i];
        red[0] = x;
    }
    __syncthreads();
    outv[(size_t)b * LC + tid] = e / red[0];
}

__global__ void __launch_bounds__(256)
attn_c2q(const float* __restrict__ a, const float* __restrict__ q_out,
         float* __restrict__ c2q)
{
    __shared__ float As[16][68];
    __shared__ float Bs[16][68];
    const int b = blockIdx.z, cc0 = blockIdx.y * 64, h0 = blockIdx.x * 64;
    const float* A = a + ((size_t)b * LC + cc0) * LQ;
    const float* B = q_out + (size_t)b * LQ * H2;
    const int tid = threadIdx.x;
    const int lr = tid >> 2, lk4 = (tid & 3) * 4;
    const int bk = tid >> 4, bn4 = (tid & 15) * 4;
    const int tx = tid & 15, ty = tid >> 4;
    float acc[4][4];
#pragma unroll
    for (int i = 0; i < 4; ++i)
#pragma unroll
        for (int j = 0; j < 4; ++j) acc[i][j] = 0.f;

    for (int k0 = 0; k0 < LQ; k0 += 16) {
        float4 va = *(const float4*)&A[(size_t)lr * LQ + k0 + lk4];
        As[lk4 + 0][lr] = va.x;
        As[lk4 + 1][lr] = va.y;
        As[lk4 + 2][lr] = va.z;
        As[lk4 + 3][lr] = va.w;
        float4 vb = *(const float4*)&B[(size_t)(k0 + bk) * H2 + h0 + bn4];
        *(float4*)&Bs[bk][bn4] = vb;
        __syncthreads();
#pragma unroll
        for (int k = 0; k < 16; ++k) {
            float4 av = *(const float4*)&As[k][ty * 4];
            float4 bv = *(const float4*)&Bs[k][tx * 4];
            float am[4] = {av.x, av.y, av.z, av.w};
            float bn[4] = {bv.x, bv.y, bv.z, bv.w};
#pragma unroll
            for (int i = 0; i < 4; ++i)
#pragma unroll
                for (int j = 0; j < 4; ++j) acc[i][j] += am[i] * bn[j];
        }
        __syncthreads();
    }
#pragma unroll
    for (int i = 0; i < 4; ++i)
#pragma unroll
        for (int j = 0; j < 4; ++j)
            c2q[((size_t)b * LC + cc0 + ty * 4 + i) * H2 + h0 + tx * 4 + j] = acc[i][j];
}

__global__ void attn_q2c(const float* __restrict__ batt, const float* __restrict__ c_out,
                         float* __restrict__ q2c)
{
    int b = blockIdx.y;
    int h = blockIdx.x * 128 + threadIdx.x;
    const float* C = c_out + (size_t)b * LC * H2;
    const float* w = batt + (size_t)b * LC;
    float acc = 0.f;
    for (int cc = 0; cc < LC; ++cc) acc += w[cc] * C[(size_t)cc * H2 + h];
    q2c[(size_t)b * H2 + h] = acc;
}

__global__ void build_G(const float* __restrict__ c_out, const float* __restrict__ c2q,
                        const float* __restrict__ q2c, float* __restrict__ G)
{
    size_t i = (size_t)blockIdx.x * blockDim.x + threadIdx.x;
    const size_t total = (size_t)BB * LC * (H2 / 4);
    if (i >= total) return;
    int h4 = (int)(i % (H2 / 4));
    size_t r = i / (H2 / 4);
    int b = (int)(r / LC);
    float4 co = ((const float4*)c_out)[r * (H2 / 4) + h4];
    float4 cq = ((const float4*)c2q)[r * (H2 / 4) + h4];
    float4 q2 = ((const float4*)q2c)[(size_t)b * (H2 / 4) + h4];
    float4* Gr = (float4*)(G + r * H8);
    Gr[h4] = co;
    Gr[(H2 / 4) + h4] = cq;
    Gr[2 * (H2 / 4) + h4] = make_float4(co.x * cq.x, co.y * cq.y, co.z * cq.z, co.w * cq.w);
    Gr[3 * (H2 / 4) + h4] = make_float4(co.x * q2.x, co.y * q2.y, co.z * q2.z, co.w * q2.w);
}

// ---------------------------------------------------------------------------
extern "C" void kernel_launch(void* const* d_in, const int* in_sizes, int n_in,
                              void* d_out, int out_size)
{
    const int*   q       = (const int*)  d_in[0];
    const int*   c       = (const int*)  d_in[1];
    const float* emb     = (const float*)d_in[2];
    const float* Wih_q   = (const float*)d_in[3];
    const float* Whh_q   = (const float*)d_in[4];
    const float* b_q     = (const float*)d_in[5];
    const float* Wih_c   = (const float*)d_in[6];
    const float* Whh_c   = (const float*)d_in[7];
    const float* b_c     = (const float*)d_in[8];
    const float* Wih_m   = (const float*)d_in[9];
    const float* Whh_m   = (const float*)d_in[10];
    const float* b_m     = (const float*)d_in[11];
    const float* sim_w   = (const float*)d_in[12];
    const float* sim_b   = (const float*)d_in[13];
    const float* start_w = (const float*)d_in[14];
    const float* start_b = (const float*)d_in[15];
    const float* end_w   = (const float*)d_in[16];
    const float* end_b   = (const float*)d_in[17];
    float* out = (float*)d_out;

    float *qemb, *cemb, *xw, *qout, *cout, *S, *smax, *batt, *cw, *qw, *c2q, *q2c, *G, *M;
    cudaGetSymbolAddress((void**)&qemb, g_qemb);
    cudaGetSymbolAddress((void**)&cemb, g_cemb);
    cudaGetSymbolAddress((void**)&xw,   g_xw);
    cudaGetSymbolAddress((void**)&qout, g_qout);
    cudaGetSymbolAddress((void**)&cout, g_cout);
    cudaGetSymbolAddress((void**)&S,    g_S);
    cudaGetSymbolAddress((void**)&smax, g_smax);
    cudaGetSymbolAddress((void**)&batt, g_batt);
    cudaGetSymbolAddress((void**)&cw,   g_cw);
    cudaGetSymbolAddress((void**)&qw,   g_qw);
    cudaGetSymbolAddress((void**)&c2q,  g_c2q);
    cudaGetSymbolAddress((void**)&q2c,  g_q2c);
    cudaGetSymbolAddress((void**)&G,    g_G);
    cudaGetSymbolAddress((void**)&M,    g_M);

    cudaFuncSetAttribute(lstm_scan, cudaFuncAttributeMaxDynamicSharedMemorySize, LSTM_SMEM);
    const int gemm_smem = 4 * STILE * (int)sizeof(float);
    cudaFuncSetAttribute(gemm_tf32, cudaFuncAttributeMaxDynamicSharedMemorySize, gemm_smem);

    gather_emb<<<(BB * LQ * EE + 255) / 256, 256>>>(q, emb, qemb, BB * LQ * EE);
    gather_emb<<<(BB * LC * EE + 255) / 256, 256>>>(c, emb, cemb, BB * LC * EE);

    for (int d = 0; d < 2; ++d)
        gemm_tf32<<<dim3(G4 / 128, (BB * LQ) / 128), 256, gemm_smem>>>(
            qemb, Wih_q + (size_t)d * G4 * EE, b_q + (size_t)d * G4,
            xw + (size_t)d * BB * LQ * G4, BB * LQ, G4, EE);
    lstm_scan<<<128, 256, LSTM_SMEM>>>(xw, Whh_q, qout, LQ);

    for (int d = 0; d < 2; ++d)
        gemm_tf32<<<dim3(G4 / 128, (BB * LC) / 128), 256, gemm_smem>>>(
            cemb, Wih_c + (size_t)d * G4 * EE, b_c + (size_t)d * G4,
            xw + (size_t)d * BB * LC * G4, BB * LC, G4, EE);
    lstm_scan<<<128, 256, LSTM_SMEM>>>(xw, Whh_c, cout, LC);

    rowdot<<<(BB * LC) / 8, 256>>>(cout, sim_w, nullptr, cw, BB * LC);
    rowdot<<<(BB * LQ) / 8, 256>>>(qout, sim_w + H2, nullptr, qw, BB * LQ);
    attn_S<<<dim3(LC / 64, BB), 256>>>(cout, qout, sim_w, sim_b, cw, qw, S);
    softmax64<<<(BB * LC) / 8, 256>>>(S, smax, BB * LC);
    softmax512<<<BB, 512>>>(smax, batt);
    attn_c2q<<<dim3(H2 / 64, LC / 64, BB), 256>>>(S, qout, c2q);
    attn_q2c<<<dim3(H2 / 128, BB), 128>>>(batt, cout, q2c);
    build_G<<<(int)(((size_t)BB * LC * (H2 / 4) + 255) / 256), 256>>>(cout, c2q, q2c, G);

    for (int d = 0; d < 2; ++d)
        gemm_tf32<<<dim3(G4 / 128, (BB * LC) / 128), 256, gemm_smem>>>(
            G, Wih_m + (size_t)d * G4 * H8, b_m + (size_t)d * G4,
            xw + (size_t)d * BB * LC * G4, BB * LC, G4, H8);
    lstm_scan<<<128, 256, LSTM_SMEM>>>(xw, Whh_m, M, LC);

    rowdot<<<(BB * LC) / 8, 256>>>(M, start_w, start_b, out, BB * LC);
    rowdot<<<(BB * LC) / 8, 256>>>(M, end_w, end_b, out + (size_t)BB * LC, BB * LC);
}

// round 7
// speedup vs baseline: 1.0307x; 1.0307x over previous
#include <cuda_runtime.h>
#include <cuda_bf16.h>
#include <math.h>
#include <stdint.h>

#define VV   32000
#define EE   300
#define HH   256
#define G4   1024
#define H2   512
#define H8   2048
#define BB   64
#define LQ   64
#define LC   512

__device__ float g_qemb[(size_t)BB * LQ * EE];
__device__ float g_cemb[(size_t)BB * LC * EE];
__device__ float g_xw  [(size_t)2 * BB * LC * G4];
__device__ float g_qout[(size_t)BB * LQ * H2];
__device__ float g_cout[(size_t)BB * LC * H2];
__device__ float g_S   [(size_t)BB * LC * LQ];
__device__ float g_smax[(size_t)BB * LC];
__device__ float g_batt[(size_t)BB * LC];
__device__ float g_cw  [(size_t)BB * LC];
__device__ float g_qw  [(size_t)BB * LQ];
__device__ float g_c2q [(size_t)BB * LC * H2];
__device__ float g_q2c [(size_t)BB * H2];
__device__ float g_G   [(size_t)BB * LC * H8];
__device__ float g_M   [(size_t)BB * LC * H2];
__device__ float g_h   [(size_t)2 * HH * BB];
__device__ volatile unsigned g_flags[128];
__device__ volatile unsigned g_gen;

__device__ __forceinline__ float sigmoidf_(float x) { return 1.f / (1.f + expf(-x)); }

__device__ __forceinline__ uint32_t f2tf32(float x)
{
    uint32_t r;
    asm("cvt.rna.tf32.f32 %0, %1;" : "=r"(r) : "f"(x));
    return r;
}

// ---------------------------------------------------------------------------
__global__ void gather_emb(const int* __restrict__ tok, const float* __restrict__ emb,
                           float* __restrict__ out, int total)
{
    int i = blockIdx.x * blockDim.x + threadIdx.x;
    if (i >= total) return;
    int row = i / EE;
    int e   = i - row * EE;
    out[i] = emb[(size_t)tok[row] * EE + e];
}

// ---------------------------------------------------------------------------
// tf32 mma.sync GEMM  C = A[M,K] * B[N,K]^T + bias  (measured 67 TF/s)
// ---------------------------------------------------------------------------
#define SROW 36
#define STILE (128 * SROW)

__device__ __forceinline__ void gtile_load(const float* __restrict__ P, int row_base,
                                           int K, int k0, int tid, float4* r)
{
#pragma unroll
    for (int i = 0; i < 4; ++i) {
        int idx = tid + i * 256;
        int row = idx >> 3, c4 = idx & 7;
        int kcol = k0 + c4 * 4;
        float4 v = make_float4(0.f, 0.f, 0.f, 0.f);
        if (kcol + 4 <= K)
            v = *(const float4*)&P[(size_t)(row_base + row) * K + kcol];
        r[i] = v;
    }
}

__device__ __forceinline__ void stile_store(float* Sb, int tid, const float4* r)
{
#pragma unroll
    for (int i = 0; i < 4; ++i) {
        int idx = tid + i * 256;
        int row = idx >> 3, c4 = idx & 7;
        float* p = Sb + row * SROW + c4 * 4;
        p[0] = __uint_as_float(f2tf32(r[i].x));
        p[1] = __uint_as_float(f2tf32(r[i].y));
        p[2] = __uint_as_float(f2tf32(r[i].z));
        p[3] = __uint_as_float(f2tf32(r[i].w));
    }
}

__global__ void __launch_bounds__(256)
gemm_tf32(const float* __restrict__ A, const float* __restrict__ B,
          const float* __restrict__ bias, float* __restrict__ C,
          int M, int N, int K)
{
    extern __shared__ float sh[];
    float* Asm = sh;
    float* Bsm = sh + 2 * STILE;

    const int tid  = threadIdx.x;
    const int lane = tid & 31;
    const int warp = tid >> 5;
    const int g = lane >> 2, t = lane & 3;
    const int m0 = (warp & 3) * 32;
    const int n0 = (warp >> 2) * 64;
    const int bm = blockIdx.y * 128;
    const int bn = blockIdx.x * 128;

    float acc[2][8][4];
#pragma unroll
    for (int mi = 0; mi < 2; ++mi)
#pragma unroll
        for (int ni = 0; ni < 8; ++ni)
#pragma unroll
            for (int k = 0; k < 4; ++k) acc[mi][ni][k] = 0.f;

    const int nk = (K + 31) >> 5;
    float4 pa[4], pb[4];

    gtile_load(A, bm, K, 0, tid, pa);
    gtile_load(B, bn, K, 0, tid, pb);
    stile_store(Asm, tid, pa);
    stile_store(Bsm, tid, pb);
    __syncthreads();

    int buf = 0;
    for (int kt = 0; kt < nk; ++kt) {
        if (kt + 1 < nk) {
            gtile_load(A, bm, K, (kt + 1) * 32, tid, pa);
            gtile_load(B, bn, K, (kt + 1) * 32, tid, pb);
        }
        const float* Ab = Asm + buf * STILE;
        const float* Bb = Bsm + buf * STILE;
#pragma unroll
        for (int kk = 0; kk < 32; kk += 8) {
            uint32_t af[2][4];
#pragma unroll
            for (int mi = 0; mi < 2; ++mi) {
                const float* ap = Ab + (m0 + mi * 16) * SROW + kk;
                af[mi][0] = __float_as_uint(ap[g * SROW + t]);
                af[mi][1] = __float_as_uint(ap[(g + 8) * SROW + t]);
                af[mi][2] = __float_as_uint(ap[g * SROW + t + 4]);
                af[mi][3] = __float_as_uint(ap[(g + 8) * SROW + t + 4]);
            }
            uint32_t bf[8][2];
#pragma unroll
            for (int ni = 0; ni < 8; ++ni) {
                const float* bp = Bb + (n0 + ni * 8) * SROW + kk;
                bf[ni][0] = __float_as_uint(bp[g * SROW + t]);
                bf[ni][1] = __float_as_uint(bp[g * SROW + t + 4]);
            }
#pragma unroll
            for (int mi = 0; mi < 2; ++mi)
#pragma unroll
                for (int ni = 0; ni < 8; ++ni)
                    asm volatile(
                        "mma.sync.aligned.m16n8k8.row.col.f32.tf32.tf32.f32 "
                        "{%0,%1,%2,%3}, {%4,%5,%6,%7}, {%8,%9}, {%0,%1,%2,%3};\n"
                        : "+f"(acc[mi][ni][0]), "+f"(acc[mi][ni][1]),
                          "+f"(acc[mi][ni][2]), "+f"(acc[mi][ni][3])
                        : "r"(af[mi][0]), "r"(af[mi][1]), "r"(af[mi][2]), "r"(af[mi][3]),
                          "r"(bf[ni][0]), "r"(bf[ni][1]));
        }
        if (kt + 1 < nk) {
            __syncthreads();
            stile_store(Asm + (buf ^ 1) * STILE, tid, pa);
            stile_store(Bsm + (buf ^ 1) * STILE, tid, pb);
            __syncthreads();
            buf ^= 1;
        }
    }
#pragma unroll
    for (int mi = 0; mi < 2; ++mi) {
#pragma unroll
        for (int ni = 0; ni < 8; ++ni) {
            int row0 = bm + m0 + mi * 16 + g;
            int col  = bn + n0 + ni * 8 + t * 2;
            float2 bv = make_float2(0.f, 0.f);
            if (bias) bv = *(const float2*)&bias[col];
            *(float2*)&C[(size_t)row0 * N + col] =
                make_float2(acc[mi][ni][0] + bv.x, acc[mi][ni][1] + bv.y);
            *(float2*)&C[(size_t)(row0 + 8) * N + col] =
                make_float2(acc[mi][ni][2] + bv.x, acc[mi][ni][3] + bv.y);
        }
    }
}

// ---------------------------------------------------------------------------
// Persistent BiLSTM scan (R3 compute) with flag-array grid barrier:
// one cumulative fence per BLOCK per step; block 0 aggregates 128 flags in
// parallel and releases a generation word. No atomics, no per-thread fences.
// ---------------------------------------------------------------------------
__global__ void lstm_scan(const float* __restrict__ xW, const float* __restrict__ Whh,
                          float* __restrict__ out, int T)
{
    extern __shared__ float sh[];
    float* h_sh   = sh;                    // [256][64]
    float* whh_sh = sh + HH * BB;          // [16][256]
    float* xw_sh  = whh_sh + 16 * HH;      // [64][16]

    const int tid = threadIdx.x;
    const int bid = blockIdx.x;
    const int dir = bid >> 6;
    const int jc  = bid & 63;
    const int j0  = jc * 4;
    const int b   = tid & 63;
    const int jj  = tid >> 6;
    const int j   = j0 + jj;

    const unsigned gen0 = g_gen;           // consistent: no writer since last kernel

    const float* WhhD = Whh + (size_t)dir * G4 * HH;
    for (int idx = tid; idx < 16 * 64; idx += 256) {
        int row = idx >> 6;
        int k4  = (idx & 63) << 2;
        int g = row >> 2, jr = row & 3;
        float4 v = *(const float4*)&WhhD[(size_t)(g * HH + j0 + jr) * HH + k4];
        *(float4*)&whh_sh[row * HH + k4] = v;
    }

    const float* xWD = xW + (size_t)dir * BB * T * G4;
    float*       hD  = g_h + (size_t)dir * HH * BB;

    float creg = 0.f;
    const int lb = tid >> 2, lg = tid & 3;

    for (int s = 0; s < T; ++s) {
        const int tt = dir ? (T - 1 - s) : s;
        {
            float4 v = *(const float4*)&xWD[((size_t)lb * T + tt) * G4 + lg * HH + j0];
            *(float4*)&xw_sh[(lb * 4 + lg) * 4] = v;
        }
        if (s > 0) {
#pragma unroll
            for (int i = 0; i < 16; ++i) {
                int idx4 = tid + i * 256;
                float4 v = __ldcg((const float4*)hD + idx4);
                ((float4*)h_sh)[idx4] = v;
            }
        }
        __syncthreads();

        float a0 = xw_sh[b * 16 + 0 * 4 + jj];
        float a1 = xw_sh[b * 16 + 1 * 4 + jj];
        float a2 = xw_sh[b * 16 + 2 * 4 + jj];
        float a3 = xw_sh[b * 16 + 3 * 4 + jj];

        if (s > 0) {
            const float* w0 = &whh_sh[(0 * 4 + jj) * HH];
            const float* w1 = &whh_sh[(1 * 4 + jj) * HH];
            const float* w2 = &whh_sh[(2 * 4 + jj) * HH];
            const float* w3 = &whh_sh[(3 * 4 + jj) * HH];
#pragma unroll 8
            for (int k = 0; k < HH; k += 4) {
                float h0 = h_sh[(k + 0) * BB + b];
                float h1 = h_sh[(k + 1) * BB + b];
                float h2 = h_sh[(k + 2) * BB + b];
                float h3 = h_sh[(k + 3) * BB + b];
                float4 v0 = *(const float4*)&w0[k];
                float4 v1 = *(const float4*)&w1[k];
                float4 v2 = *(const float4*)&w2[k];
                float4 v3 = *(const float4*)&w3[k];
                a0 += v0.x * h0; a0 += v0.y * h1; a0 += v0.z * h2; a0 += v0.w * h3;
                a1 += v1.x * h0; a1 += v1.y * h1; a1 += v1.z * h2; a1 += v1.w * h3;
                a2 += v2.x * h0; a2 += v2.y * h1; a2 += v2.z * h2; a2 += v2.w * h3;
                a3 += v3.x * h0; a3 += v3.y * h1; a3 += v3.z * h2; a3 += v3.w * h3;
            }
        }

        float ig = sigmoidf_(a0);
        float fg = sigmoidf_(a1);
        float gg = tanhf(a2);
        float og = sigmoidf_(a3);
        creg = fg * creg + ig * gg;
        float hh = og * tanhf(creg);

        __stcg(&hD[j * BB + b], hh);
        out[((size_t)b * T + tt) * H2 + dir * HH + j] = hh;

        if (s + 1 < T) {
            const unsigned tgt = gen0 + (unsigned)(s + 1);
            __syncthreads();                       // all h stores issued (cta order)
            if (tid == 0) {
                asm volatile("fence.acq_rel.gpu;" ::: "memory");   // publish CTA's stores
                g_flags[bid] = tgt;
            }
            if (bid == 0 && tid < 128) {
                while ((int)(g_flags[tid] - tgt) < 0) { }
            }
            __syncthreads();
            if (bid == 0 && tid == 0) {
                asm volatile("fence.acq_rel.gpu;" ::: "memory");
                g_gen = tgt;
            }
            if (tid == 0) {
                while ((int)(g_gen - tgt) < 0) { }
                asm volatile("fence.acq_rel.gpu;" ::: "memory");   // acquire
            }
            __syncthreads();
        }
    }
}

// ---------------------------------------------------------------------------
__global__ void rowdot(const float* __restrict__ A, const float* __restrict__ w,
                       const float* __restrict__ bias, float* __restrict__ out, int rows)
{
    int gw = (blockIdx.x * blockDim.x + threadIdx.x) >> 5;
    int lane = threadIdx.x & 31;
    if (gw >= rows) return;
    const float* row = A + (size_t)gw * H2;
    float s = 0.f;
#pragma unroll
    for (int i = 0; i < 16; ++i) s += row[lane + i * 32] * w[lane + i * 32];
#pragma unroll
    for (int off = 16; off; off >>= 1) s += __shfl_xor_sync(0xffffffffu, s, off);
    if (lane == 0) out[gw] = s + (bias ? bias[0] : 0.f);
}

__global__ void __launch_bounds__(256)
attn_S(const float* __restrict__ c_out, const float* __restrict__ q_out,
       const float* __restrict__ sim_w, const float* __restrict__ sim_b,
       const float* __restrict__ cw, const float* __restrict__ qw,
       float* __restrict__ S)
{
    __shared__ float As[16][68];
    __shared__ float Bs[16][68];
    const int b = blockIdx.y, cc0 = blockIdx.x * 64;
    const float* A  = c_out + ((size_t)b * LC + cc0) * H2;
    const float* Bq = q_out + (size_t)b * LQ * H2;
    const float* wcq = sim_w + 2 * H2;
    const int tid = threadIdx.x;
    const int lr = tid >> 2, lk4 = (tid & 3) * 4;
    const int tx = tid & 15, ty = tid >> 4;
    float acc[4][4];
#pragma unroll
    for (int i = 0; i < 4; ++i)
#pragma unroll
        for (int j = 0; j < 4; ++j) acc[i][j] = 0.f;

    for (int k0 = 0; k0 < H2; k0 += 16) {
        float4 va = *(const float4*)&A[(size_t)lr * H2 + k0 + lk4];
        float4 wv = *(const float4*)&wcq[k0 + lk4];
        As[lk4 + 0][lr] = va.x * wv.x;
        As[lk4 + 1][lr] = va.y * wv.y;
        As[lk4 + 2][lr] = va.z * wv.z;
        As[lk4 + 3][lr] = va.w * wv.w;
        float4 vb = *(const float4*)&Bq[(size_t)lr * H2 + k0 + lk4];
        Bs[lk4 + 0][lr] = vb.x;
        Bs[lk4 + 1][lr] = vb.y;
        Bs[lk4 + 2][lr] = vb.z;
        Bs[lk4 + 3][lr] = vb.w;
        __syncthreads();
#pragma unroll
        for (int k = 0; k < 16; ++k) {
            float4 av = *(const float4*)&As[k][ty * 4];
            float4 bv = *(const float4*)&Bs[k][tx * 4];
            float am[4] = {av.x, av.y, av.z, av.w};
            float bn[4] = {bv.x, bv.y, bv.z, bv.w};
#pragma unroll
            for (int i = 0; i < 4; ++i)
#pragma unroll
                for (int j = 0; j < 4; ++j) acc[i][j] += am[i] * bn[j];
        }
        __syncthreads();
    }
    float sb = sim_b[0];
#pragma unroll
    for (int i = 0; i < 4; ++i) {
        int cc = cc0 + ty * 4 + i;
        float cwv = cw[b * LC + cc];
#pragma unroll
        for (int j = 0; j < 4; ++j) {
            int qq = tx * 4 + j;
            S[((size_t)b * LC + cc) * LQ + qq] = acc[i][j] + cwv + qw[b * LQ + qq] + sb;
        }
    }
}

__global__ void softmax64(float* __restrict__ S, float* __restrict__ smax, int rows)
{
    int gw = (blockIdx.x * blockDim.x + threadIdx.x) >> 5;
    int lane = threadIdx.x & 31;
    if (gw >= rows) return;
    float* row = S + (size_t)gw * LQ;
    float v0 = row[lane], v1 = row[lane + 32];
    float m = fmaxf(v0, v1);
#pragma unroll
    for (int off = 16; off; off >>= 1) m = fmaxf(m, __shfl_xor_sync(0xffffffffu, m, off));
    float e0 = expf(v0 - m), e1 = expf(v1 - m);
    float s = e0 + e1;
#pragma unroll
    for (int off = 16; off; off >>= 1) s += __shfl_xor_sync(0xffffffffu, s, off);
    float inv = 1.f / s;
    row[lane] = e0 * inv;
    row[lane + 32] = e1 * inv;
    if (lane == 0) smax[gw] = m;
}

__global__ void softmax512(const float* __restrict__ in, float* __restrict__ outv)
{
    __shared__ float red[16];
    int b = blockIdx.x, tid = threadIdx.x;
    float v = in[(size_t)b * LC + tid];
    float m = v;
#pragma unroll
    for (int off = 16; off; off >>= 1) m = fmaxf(m, __shfl_xor_sync(0xffffffffu, m, off));
    if ((tid & 31) == 0) red[tid >> 5] = m;
    __syncthreads();
    if (tid == 0) {
        float x = red[0];
        for (int i = 1; i < 16; ++i) x = fmaxf(x, red[i]);
        red[0] = x;
    }
    __syncthreads();
    m = red[0];
    __syncthreads();
    float e = expf(v - m);
    float s = e;
#pragma unroll
    for (int off = 16; off; off >>= 1) s += __shfl_xor_sync(0xffffffffu, s, off);
    if ((tid & 31) == 0) red[tid >> 5] = s;
    __syncthreads();
    if (tid == 0) {
        float x = 0.f;
        for (int i = 0; i < 16; ++i) x += red[i];
        red[0] = x;
    }
    __syncthreads();
    outv[(size_t)b * LC + tid] = e / red[0];
}

__global__ void __launch_bounds__(256)
attn_c2q(const float* __restrict__ a, const float* __restrict__ q_out,
         float* __restrict__ c2q)
{
    __shared__ float As[16][68];
    __shared__ float Bs[16][68];
    const int b = blockIdx.z, cc0 = blockIdx.y * 64, h0 = blockIdx.x * 64;
    const float* A = a + ((size_t)b * LC + cc0) * LQ;
    const float* B = q_out + (size_t)b * LQ * H2;
    const int tid = threadIdx.x;
    const int lr = tid >> 2, lk4 = (tid & 3) * 4;
    const int bk = tid >> 4, bn4 = (tid & 15) * 4;
    const int tx = tid & 15, ty = tid >> 4;
    float acc[4][4];
#pragma unroll
    for (int i = 0; i < 4; ++i)
#pragma unroll
        for (int j = 0; j < 4; ++j) acc[i][j] = 0.f;

    for (int k0 = 0; k0 < LQ; k0 += 16) {
        float4 va = *(const float4*)&A[(size_t)lr * LQ + k0 + lk4];
        As[lk4 + 0][lr] = va.x;
        As[lk4 + 1][lr] = va.y;
        As[lk4 + 2][lr] = va.z;
        As[lk4 + 3][lr] = va.w;
        float4 vb = *(const float4*)&B[(size_t)(k0 + bk) * H2 + h0 + bn4];
        *(float4*)&Bs[bk][bn4] = vb;
        __syncthreads();
#pragma unroll
        for (int k = 0; k < 16; ++k) {
            float4 av = *(const float4*)&As[k][ty * 4];
            float4 bv = *(const float4*)&Bs[k][tx * 4];
            float am[4] = {av.x, av.y, av.z, av.w};
            float bn[4] = {bv.x, bv.y, bv.z, bv.w};
#pragma unroll
            for (int i = 0; i < 4; ++i)
#pragma unroll
                for (int j = 0; j < 4; ++j) acc[i][j] += am[i] * bn[j];
        }
        __syncthreads();
    }
#pragma unroll
    for (int i = 0; i < 4; ++i)
#pragma unroll
        for (int j = 0; j < 4; ++j)
            c2q[((size_t)b * LC + cc0 + ty * 4 + i) * H2 + h0 + tx * 4 + j] = acc[i][j];
}

__global__ void attn_q2c(const float* __restrict__ batt, const float* __restrict__ c_out,
                         float* __restrict__ q2c)
{
    int b = blockIdx.y;
    int h = blockIdx.x * 128 + threadIdx.x;
    const float* C = c_out + (size_t)b * LC * H2;
    const float* w = batt + (size_t)b * LC;
    float acc = 0.f;
    for (int cc = 0; cc < LC; ++cc) acc += w[cc] * C[(size_t)cc * H2 + h];
    q2c[(size_t)b * H2 + h] = acc;
}

__global__ void build_G(const float* __restrict__ c_out, const float* __restrict__ c2q,
                        const float* __restrict__ q2c, float* __restrict__ G)
{
    size_t i = (size_t)blockIdx.x * blockDim.x + threadIdx.x;
    const size_t total = (size_t)BB * LC * (H2 / 4);
    if (i >= total) return;
    int h4 = (int)(i % (H2 / 4));
    size_t r = i / (H2 / 4);
    int b = (int)(r / LC);
    float4 co = ((const float4*)c_out)[r * (H2 / 4) + h4];
    float4 cq = ((const float4*)c2q)[r * (H2 / 4) + h4];
    float4 q2 = ((const float4*)q2c)[(size_t)b * (H2 / 4) + h4];
    float4* Gr = (float4*)(G + r * H8);
    Gr[h4] = co;
    Gr[(H2 / 4) + h4] = cq;
    Gr[2 * (H2 / 4) + h4] = make_float4(co.x * cq.x, co.y * cq.y, co.z * cq.z, co.w * cq.w);
    Gr[3 * (H2 / 4) + h4] = make_float4(co.x * q2.x, co.y * q2.y, co.z * q2.z, co.w * q2.w);
}

// ---------------------------------------------------------------------------
extern "C" void kernel_launch(void* const* d_in, const int* in_sizes, int n_in,
                              void* d_out, int out_size)
{
    const int*   q       = (const int*)  d_in[0];
    const int*   c       = (const int*)  d_in[1];
    const float* emb     = (const float*)d_in[2];
    const float* Wih_q   = (const float*)d_in[3];
    const float* Whh_q   = (const float*)d_in[4];
    const float* b_q     = (const float*)d_in[5];
    const float* Wih_c   = (const float*)d_in[6];
    const float* Whh_c   = (const float*)d_in[7];
    const float* b_c     = (const float*)d_in[8];
    const float* Wih_m   = (const float*)d_in[9];
    const float* Whh_m   = (const float*)d_in[10];
    const float* b_m     = (const float*)d_in[11];
    const float* sim_w   = (const float*)d_in[12];
    const float* sim_b   = (const float*)d_in[13];
    const float* start_w = (const float*)d_in[14];
    const float* start_b = (const float*)d_in[15];
    const float* end_w   = (const float*)d_in[16];
    const float* end_b   = (const float*)d_in[17];
    float* out = (float*)d_out;

    float *qemb, *cemb, *xw, *qout, *cout, *S, *smax, *batt, *cw, *qw, *c2q, *q2c, *G, *M;
    cudaGetSymbolAddress((void**)&qemb, g_qemb);
    cudaGetSymbolAddress((void**)&cemb, g_cemb);
    cudaGetSymbolAddress((void**)&xw,   g_xw);
    cudaGetSymbolAddress((void**)&qout, g_qout);
    cudaGetSymbolAddress((void**)&cout, g_cout);
    cudaGetSymbolAddress((void**)&S,    g_S);
    cudaGetSymbolAddress((void**)&smax, g_smax);
    cudaGetSymbolAddress((void**)&batt, g_batt);
    cudaGetSymbolAddress((void**)&cw,   g_cw);
    cudaGetSymbolAddress((void**)&qw,   g_qw);
    cudaGetSymbolAddress((void**)&c2q,  g_c2q);
    cudaGetSymbolAddress((void**)&q2c,  g_q2c);
    cudaGetSymbolAddress((void**)&G,    g_G);
    cudaGetSymbolAddress((void**)&M,    g_M);

    const int lstm_smem = (HH * BB + 16 * HH + 64 * 16) * (int)sizeof(float); // 86016 B
    cudaFuncSetAttribute(lstm_scan, cudaFuncAttributeMaxDynamicSharedMemorySize, lstm_smem);
    const int gemm_smem = 4 * STILE * (int)sizeof(float);
    cudaFuncSetAttribute(gemm_tf32, cudaFuncAttributeMaxDynamicSharedMemorySize, gemm_smem);

    gather_emb<<<(BB * LQ * EE + 255) / 256, 256>>>(q, emb, qemb, BB * LQ * EE);
    gather_emb<<<(BB * LC * EE + 255) / 256, 256>>>(c, emb, cemb, BB * LC * EE);

    for (int d = 0; d < 2; ++d)
        gemm_tf32<<<dim3(G4 / 128, (BB * LQ) / 128), 256, gemm_smem>>>(
            qemb, Wih_q + (size_t)d * G4 * EE, b_q + (size_t)d * G4,
            xw + (size_t)d * BB * LQ * G4, BB * LQ, G4, EE);
    lstm_scan<<<128, 256, lstm_smem>>>(xw, Whh_q, qout, LQ);

    for (int d = 0; d < 2; ++d)
        gemm_tf32<<<dim3(G4 / 128, (BB * LC) / 128), 256, gemm_smem>>>(
            cemb, Wih_c + (size_t)d * G4 * EE, b_c + (size_t)d * G4,
            xw + (size_t)d * BB * LC * G4, BB * LC, G4, EE);
    lstm_scan<<<128, 256, lstm_smem>>>(xw, Whh_c, cout, LC);

    rowdot<<<(BB * LC) / 8, 256>>>(cout, sim_w, nullptr, cw, BB * LC);
    rowdot<<<(BB * LQ) / 8, 256>>>(qout, sim_w + H2, nullptr, qw, BB * LQ);
    attn_S<<<dim3(LC / 64, BB), 256>>>(cout, qout, sim_w, sim_b, cw, qw, S);
    softmax64<<<(BB * LC) / 8, 256>>>(S, smax, BB * LC);
    softmax512<<<BB, 512>>>(smax, batt);
    attn_c2q<<<dim3(H2 / 64, LC / 64, BB), 256>>>(S, qout, c2q);
    attn_q2c<<<dim3(H2 / 128, BB), 128>>>(batt, cout, q2c);
    build_G<<<(int)(((size_t)BB * LC * (H2 / 4) + 255) / 256), 256>>>(cout, c2q, q2c, G);

    for (int d = 0; d < 2; ++d)
        gemm_tf32<<<dim3(G4 / 128, (BB * LC) / 128), 256, gemm_smem>>>(
            G, Wih_m + (size_t)d * G4 * H8, b_m + (size_t)d * G4,
            xw + (size_t)d * BB * LC * G4, BB * LC, G4, H8);
    lstm_scan<<<128, 256, lstm_smem>>>(xw, Whh_m, M, LC);

    rowdot<<<(BB * LC) / 8, 256>>>(M, start_w, start_b, out, BB * LC);
    rowdot<<<(BB * LC) / 8, 256>>>(M, end_w, end_b, out + (size_t)BB * LC, BB * LC);
}

// round 9
// speedup vs baseline: 1.2637x; 1.2260x over previous
#include <cuda_runtime.h>
#include <cuda_bf16.h>
#include <math.h>
#include <stdint.h>

#define EE   300
#define HH   256
#define G4   1024
#define H2   512
#define H8   2048
#define BB   64
#define LQ   64
#define LC   512

__device__ float g_qemb[(size_t)BB * LQ * EE];
__device__ float g_cemb[(size_t)BB * LC * EE];
__device__ float g_xw  [(size_t)2 * BB * LC * G4];
__device__ float g_qout[(size_t)BB * LQ * H2];
__device__ float g_cout[(size_t)BB * LC * H2];
__device__ float g_S   [(size_t)BB * LC * LQ];
__device__ float g_smax[(size_t)BB * LC];
__device__ float g_batt[(size_t)BB * LC];
__device__ float g_cw  [(size_t)BB * LC];
__device__ float g_qw  [(size_t)BB * LQ];
__device__ float g_c2q [(size_t)BB * LC * H2];
__device__ float g_q2c [(size_t)BB * H2];
__device__ float g_G   [(size_t)BB * LC * H8];
__device__ float g_M   [(size_t)BB * LC * H2];
__device__ float g_h   [(size_t)2 * HH * BB];
__device__ float g_wcvt[(size_t)2 * G4 * H8];
__device__ unsigned g_bar_cnt = 0;
__device__ unsigned g_bar_gen = 0;

__device__ __forceinline__ float sigmoidf_(float x) { return 1.f / (1.f + expf(-x)); }

__device__ __forceinline__ uint32_t f2tf32(float x)
{
    uint32_t r;
    asm("cvt.rna.tf32.f32 %0, %1;" : "=r"(r) : "f"(x));
    return r;
}
__device__ __forceinline__ float rtf(float x) { return __uint_as_float(f2tf32(x)); }

__device__ __forceinline__ void grid_barrier(unsigned nb)
{
    __threadfence();
    __syncthreads();
    if (threadIdx.x == 0) {
        unsigned g = *(volatile unsigned*)&g_bar_gen;
        if (atomicAdd(&g_bar_cnt, 1u) == nb - 1u) {
            g_bar_cnt = 0;
            __threadfence();
            atomicAdd(&g_bar_gen, 1u);
        } else {
            while (*(volatile unsigned*)&g_bar_gen == g) { }
        }
    }
    __syncthreads();
    __threadfence();
}

__device__ __forceinline__ void cp16(uint32_t dst, const void* src)
{
    asm volatile("cp.async.cg.shared.global [%0], [%1], 16;" :: "r"(dst), "l"(src));
}
__device__ __forceinline__ uint32_t smem_u32(const void* p)
{
    uint32_t a;
    asm("{ .reg .u64 t; cvta.to.shared.u64 t, %1; cvt.u32.u64 %0, t; }" : "=r"(a) : "l"(p));
    return a;
}

// ---------------------------------------------------------------------------
__global__ void gather_emb(const int* __restrict__ tok, const float* __restrict__ emb,
                           float* __restrict__ out, int total)
{
    int i = blockIdx.x * blockDim.x + threadIdx.x;
    if (i >= total) return;
    int row = i / EE;
    int e   = i - row * EE;
    out[i] = rtf(emb[(size_t)tok[row] * EE + e]);
}

__global__ void cvt_tf32(const float* __restrict__ in, float* __restrict__ out, int n)
{
    int i = blockIdx.x * blockDim.x + threadIdx.x;
    if (i < n) out[i] = rtf(in[i]);
}

// ---------------------------------------------------------------------------
// tf32 mma.sync GEMM v2: C[M,N]=A[M,K]*B[N,K]^T + bias.
// CTA tile 128x128, 4 warps (2x2), warp tile 64x64, BK=32.
// cp.async 2-stage pipeline; A,B must be pre-rounded to tf32.
// M%128==0, N%128==0, K%4==0. 128 threads.
// ---------------------------------------------------------------------------
#define SROW 36
#define STILE (128 * SROW)               // floats per (A or B) tile

__device__ __forceinline__ void fill_tile(uint32_t sA, uint32_t sB,
                                          const float* __restrict__ A,
                                          const float* __restrict__ B,
                                          int bm, int bn, int K, int k0, int tid)
{
#pragma unroll
    for (int i = 0; i < 8; ++i) {
        int idx = tid + i * 128;
        int row = idx >> 3, c4 = idx & 7;
        int k = k0 + c4 * 4;
        uint32_t da = sA + (row * SROW + c4 * 4) * 4;
        uint32_t db = sB + (row * SROW + c4 * 4) * 4;
        if (k + 4 <= K) {
            cp16(da, &A[(size_t)(bm + row) * K + k]);
            cp16(db, &B[(size_t)(bn + row) * K + k]);
        } else {
            asm volatile("st.shared.v4.b32 [%0], {%1,%1,%1,%1};" :: "r"(da), "r"(0) : "memory");
            asm volatile("st.shared.v4.b32 [%0], {%1,%1,%1,%1};" :: "r"(db), "r"(0) : "memory");
        }
    }
}

__global__ void __launch_bounds__(128)
gemm_tf32(const float* __restrict__ A, const float* __restrict__ B,
          const float* __restrict__ bias, float* __restrict__ C,
          int M, int N, int K)
{
    extern __shared__ float sh[];        // [2][A STILE + B STILE]
    const int tid  = threadIdx.x;
    const int lane = tid & 31;
    const int warp = tid >> 5;
    const int g = lane >> 2, t = lane & 3;
    const int m0 = (warp & 1) * 64;
    const int n0 = (warp >> 1) * 64;
    const int bm = blockIdx.y * 128;
    const int bn = blockIdx.x * 128;
    const uint32_t sb = smem_u32(sh);

    float acc[4][8][4];
#pragma unroll
    for (int mi = 0; mi < 4; ++mi)
#pragma unroll
        for (int ni = 0; ni < 8; ++ni)
#pragma unroll
            for (int k = 0; k < 4; ++k) acc[mi][ni][k] = 0.f;

    const int nk = (K + 31) >> 5;
    const uint32_t stage_b = 2 * STILE * 4;   // bytes per stage (A+B)

    fill_tile(sb, sb + STILE * 4, A, B, bm, bn, K, 0, tid);
    asm volatile("cp.async.commit_group;" ::: "memory");

    int buf = 0;
    for (int kt = 0; kt < nk; ++kt) {
        if (kt + 1 < nk) {
            fill_tile(sb + (buf ^ 1) * stage_b, sb + (buf ^ 1) * stage_b + STILE * 4,
                      A, B, bm, bn, K, (kt + 1) * 32, tid);
            asm volatile("cp.async.commit_group;" ::: "memory");
            asm volatile("cp.async.wait_group 1;" ::: "memory");
        } else {
            asm volatile("cp.async.wait_group 0;" ::: "memory");
        }
        __syncthreads();

        const float* Ab = sh + buf * 2 * STILE;
        const float* Bb = Ab + STILE;
#pragma unroll
        for (int kk = 0; kk < 32; kk += 8) {
            uint32_t af[4][4];
#pragma unroll
            for (int mi = 0; mi < 4; ++mi) {
                const float* ap = Ab + (m0 + mi * 16) * SROW + kk;
                af[mi][0] = __float_as_uint(ap[g * SROW + t]);
                af[mi][1] = __float_as_uint(ap[(g + 8) * SROW + t]);
                af[mi][2] = __float_as_uint(ap[g * SROW + t + 4]);
                af[mi][3] = __float_as_uint(ap[(g + 8) * SROW + t + 4]);
            }
            uint32_t bf[8][2];
#pragma unroll
            for (int ni = 0; ni < 8; ++ni) {
                const float* bp = Bb + (n0 + ni * 8) * SROW + kk;
                bf[ni][0] = __float_as_uint(bp[g * SROW + t]);
                bf[ni][1] = __float_as_uint(bp[g * SROW + t + 4]);
            }
#pragma unroll
            for (int mi = 0; mi < 4; ++mi)
#pragma unroll
                for (int ni = 0; ni < 8; ++ni)
                    asm volatile(
                        "mma.sync.aligned.m16n8k8.row.col.f32.tf32.tf32.f32 "
                        "{%0,%1,%2,%3}, {%4,%5,%6,%7}, {%8,%9}, {%0,%1,%2,%3};\n"
                        : "+f"(acc[mi][ni][0]), "+f"(acc[mi][ni][1]),
                          "+f"(acc[mi][ni][2]), "+f"(acc[mi][ni][3])
                        : "r"(af[mi][0]), "r"(af[mi][1]), "r"(af[mi][2]), "r"(af[mi][3]),
                          "r"(bf[ni][0]), "r"(bf[ni][1]));
        }
        __syncthreads();   // all reads of buf done before its next refill
        buf ^= 1;
    }

#pragma unroll
    for (int mi = 0; mi < 4; ++mi) {
#pragma unroll
        for (int ni = 0; ni < 8; ++ni) {
            int row0 = bm + m0 + mi * 16 + g;
            int col  = bn + n0 + ni * 8 + t * 2;
            float2 bv = make_float2(0.f, 0.f);
            if (bias) bv = *(const float2*)&bias[col];
            *(float2*)&C[(size_t)row0 * N + col] =
                make_float2(acc[mi][ni][0] + bv.x, acc[mi][ni][1] + bv.y);
            *(float2*)&C[(size_t)(row0 + 8) * N + col] =
                make_float2(acc[mi][ni][2] + bv.x, acc[mi][ni][3] + bv.y);
        }
    }
}
#define GEMM_SMEM (4 * STILE * (int)sizeof(float))   // 73728 B

// ---------------------------------------------------------------------------
// Persistent BiLSTM scan — exact R3 version (best known).
// ---------------------------------------------------------------------------
__global__ void lstm_scan(const float* __restrict__ xW, const float* __restrict__ Whh,
                          float* __restrict__ out, int T)
{
    extern __shared__ float sh[];
    float* h_sh   = sh;
    float* whh_sh = sh + HH * BB;
    float* xw_sh  = whh_sh + 16 * HH;

    const int tid = threadIdx.x;
    const int dir = blockIdx.x >> 6;
    const int jc  = blockIdx.x & 63;
    const int j0  = jc * 4;
    const int b   = tid & 63;
    const int jj  = tid >> 6;
    const int j   = j0 + jj;

    const float* WhhD = Whh + (size_t)dir * G4 * HH;
    for (int idx = tid; idx < 16 * 64; idx += 256) {
        int row = idx >> 6;
        int k4  = (idx & 63) << 2;
        int g = row >> 2, jr = row & 3;
        float4 v = *(const float4*)&WhhD[(size_t)(g * HH + j0 + jr) * HH + k4];
        *(float4*)&whh_sh[row * HH + k4] = v;
    }

    const float* xWD = xW + (size_t)dir * BB * T * G4;
    float*       hD  = g_h + (size_t)dir * HH * BB;

    float creg = 0.f;
    const int lb = tid >> 2, lg = tid & 3;

    for (int s = 0; s < T; ++s) {
        const int tt = dir ? (T - 1 - s) : s;
        {
            float4 v = *(const float4*)&xWD[((size_t)lb * T + tt) * G4 + lg * HH + j0];
            *(float4*)&xw_sh[(lb * 4 + lg) * 4] = v;
        }
        if (s > 0) {
#pragma unroll
            for (int i = 0; i < 16; ++i) {
                int idx4 = tid + i * 256;
                float4 v = __ldcg((const float4*)hD + idx4);
                ((float4*)h_sh)[idx4] = v;
            }
        }
        __syncthreads();

        float a0 = xw_sh[b * 16 + 0 * 4 + jj];
        float a1 = xw_sh[b * 16 + 1 * 4 + jj];
        float a2 = xw_sh[b * 16 + 2 * 4 + jj];
        float a3 = xw_sh[b * 16 + 3 * 4 + jj];

        if (s > 0) {
            const float* w0 = &whh_sh[(0 * 4 + jj) * HH];
            const float* w1 = &whh_sh[(1 * 4 + jj) * HH];
            const float* w2 = &whh_sh[(2 * 4 + jj) * HH];
            const float* w3 = &whh_sh[(3 * 4 + jj) * HH];
#pragma unroll 8
            for (int k = 0; k < HH; k += 4) {
                float h0 = h_sh[(k + 0) * BB + b];
                float h1 = h_sh[(k + 1) * BB + b];
                float h2 = h_sh[(k + 2) * BB + b];
                float h3 = h_sh[(k + 3) * BB + b];
                float4 v0 = *(const float4*)&w0[k];
                float4 v1 = *(const float4*)&w1[k];
                float4 v2 = *(const float4*)&w2[k];
                float4 v3 = *(const float4*)&w3[k];
                a0 += v0.x * h0; a0 += v0.y * h1; a0 += v0.z * h2; a0 += v0.w * h3;
                a1 += v1.x * h0; a1 += v1.y * h1; a1 += v1.z * h2; a1 += v1.w * h3;
                a2 += v2.x * h0; a2 += v2.y * h1; a2 += v2.z * h2; a2 += v2.w * h3;
                a3 += v3.x * h0; a3 += v3.y * h1; a3 += v3.z * h2; a3 += v3.w * h3;
            }
        }

        float ig = sigmoidf_(a0);
        float fg = sigmoidf_(a1);
        float gg = tanhf(a2);
        float og = sigmoidf_(a3);
        creg = fg * creg + ig * gg;
        float hh = og * tanhf(creg);

        __stcg(&hD[j * BB + b], hh);
        out[((size_t)b * T + tt) * H2 + dir * HH + j] = hh;

        if (s + 1 < T) grid_barrier(gridDim.x);
    }
}

// ---------------------------------------------------------------------------
__global__ void rowdot(const float* __restrict__ A, const float* __restrict__ w,
                       const float* __restrict__ bias, float* __restrict__ out, int rows)
{
    int gw = (blockIdx.x * blockDim.x + threadIdx.x) >> 5;
    int lane = threadIdx.x & 31;
    if (gw >= rows) return;
    const float* row = A + (size_t)gw * H2;
    float s = 0.f;
#pragma unroll
    for (int i = 0; i < 16; ++i) s += row[lane + i * 32] * w[lane + i * 32];
#pragma unroll
    for (int off = 16; off; off >>= 1) s += __shfl_xor_sync(0xffffffffu, s, off);
    if (lane == 0) out[gw] = s + (bias ? bias[0] : 0.f);
}

__global__ void __launch_bounds__(256)
attn_S(const float* __restrict__ c_out, const float* __restrict__ q_out,
       const float* __restrict__ sim_w, const float* __restrict__ sim_b,
       const float* __restrict__ cw, const float* __restrict__ qw,
       float* __restrict__ S)
{
    __shared__ float As[16][68];
    __shared__ float Bs[16][68];
    const int b = blockIdx.y, cc0 = blockIdx.x * 64;
    const float* A  = c_out + ((size_t)b * LC + cc0) * H2;
    const float* Bq = q_out + (size_t)b * LQ * H2;
    const float* wcq = sim_w + 2 * H2;
    const int tid = threadIdx.x;
    const int lr = tid >> 2, lk4 = (tid & 3) * 4;
    const int tx = tid & 15, ty = tid >> 4;
    float acc[4][4];
#pragma unroll
    for (int i = 0; i < 4; ++i)
#pragma unroll
        for (int j = 0; j < 4; ++j) acc[i][j] = 0.f;

    for (int k0 = 0; k0 < H2; k0 += 16) {
        float4 va = *(const float4*)&A[(size_t)lr * H2 + k0 + lk4];
        float4 wv = *(const float4*)&wcq[k0 + lk4];
        As[lk4 + 0][lr] = va.x * wv.x;
        As[lk4 + 1][lr] = va.y * wv.y;
        As[lk4 + 2][lr] = va.z * wv.z;
        As[lk4 + 3][lr] = va.w * wv.w;
        float4 vb = *(const float4*)&Bq[(size_t)lr * H2 + k0 + lk4];
        Bs[lk4 + 0][lr] = vb.x;
        Bs[lk4 + 1][lr] = vb.y;
        Bs[lk4 + 2][lr] = vb.z;
        Bs[lk4 + 3][lr] = vb.w;
        __syncthreads();
#pragma unroll
        for (int k = 0; k < 16; ++k) {
            float4 av = *(const float4*)&As[k][ty * 4];
            float4 bv = *(const float4*)&Bs[k][tx * 4];
            float am[4] = {av.x, av.y, av.z, av.w};
            float bn[4] = {bv.x, bv.y, bv.z, bv.w};
#pragma unroll
            for (int i = 0; i < 4; ++i)
#pragma unroll
                for (int j = 0; j < 4; ++j) acc[i][j] += am[i] * bn[j];
        }
        __syncthreads();
    }
    float sb = sim_b[0];
#pragma unroll
    for (int i = 0; i < 4; ++i) {
        int cc = cc0 + ty * 4 + i;
        float cwv = cw[b * LC + cc];
#pragma unroll
        for (int j = 0; j < 4; ++j) {
            int qq = tx * 4 + j;
            S[((size_t)b * LC + cc) * LQ + qq] = acc[i][j] + cwv + qw[b * LQ + qq] + sb;
        }
    }
}

__global__ void softmax64(float* __restrict__ S, float* __restrict__ smax, int rows)
{
    int gw = (blockIdx.x * blockDim.x + threadIdx.x) >> 5;
    int lane = threadIdx.x & 31;
    if (gw >= rows) return;
    float* row = S + (size_t)gw * LQ;
    float v0 = row[lane], v1 = row[lane + 32];
    float m = fmaxf(v0, v1);
#pragma unroll
    for (int off = 16; off; off >>= 1) m = fmaxf(m, __shfl_xor_sync(0xffffffffu, m, off));
    float e0 = expf(v0 - m), e1 = expf(v1 - m);
    float s = e0 + e1;
#pragma unroll
    for (int off = 16; off; off >>= 1) s += __shfl_xor_sync(0xffffffffu, s, off);
    float inv = 1.f / s;
    row[lane] = e0 * inv;
    row[lane + 32] = e1 * inv;
    if (lane == 0) smax[gw] = m;
}

__global__ void softmax512(const float* __restrict__ in, float* __restrict__ outv)
{
    __shared__ float red[16];
    int b = blockIdx.x, tid = threadIdx.x;
    float v = in[(size_t)b * LC + tid];
    float m = v;
#pragma unroll
    for (int off = 16; off; off >>= 1) m = fmaxf(m, __shfl_xor_sync(0xffffffffu, m, off));
    if ((tid & 31) == 0) red[tid >> 5] = m;
    __syncthreads();
    if (tid == 0) {
        float x = red[0];
        for (int i = 1; i < 16; ++i) x = fmaxf(x, red[i]);
        red[0] = x;
    }
    __syncthreads();
    m = red[0];
    __syncthreads();
    float e = expf(v - m);
    float s = e;
#pragma unroll
    for (int off = 16; off; off >>= 1) s += __shfl_xor_sync(0xffffffffu, s, off);
    if ((tid & 31) == 0) red[tid >> 5] = s;
    __syncthreads();
    if (tid == 0) {
        float x = 0.f;
        for (int i = 0; i < 16; ++i) x += red[i];
        red[0] = x;
    }
    __syncthreads();
    outv[(size_t)b * LC + tid] = e / red[0];
}

__global__ void __launch_bounds__(256)
attn_c2q(const float* __restrict__ a, const float* __restrict__ q_out,
         float* __restrict__ c2q)
{
    __shared__ float As[16][68];
    __shared__ float Bs[16][68];
    const int b = blockIdx.z, cc0 = blockIdx.y * 64, h0 = blockIdx.x * 64;
    const float* A = a + ((size_t)b * LC + cc0) * LQ;
    const float* B = q_out + (size_t)b * LQ * H2;
    const int tid = threadIdx.x;
    const int lr = tid >> 2, lk4 = (tid & 3) * 4;
    const int bk = tid >> 4, bn4 = (tid & 15) * 4;
    const int tx = tid & 15, ty = tid >> 4;
    float acc[4][4];
#pragma unroll
    for (int i = 0; i < 4; ++i)
#pragma unroll
        for (int j = 0; j < 4; ++j) acc[i][j] = 0.f;

    for (int k0 = 0; k0 < LQ; k0 += 16) {
        float4 va = *(const float4*)&A[(size_t)lr * LQ + k0 + lk4];
        As[lk4 + 0][lr] = va.x;
        As[lk4 + 1][lr] = va.y;
        As[lk4 + 2][lr] = va.z;
        As[lk4 + 3][lr] = va.w;
        float4 vb = *(const float4*)&B[(size_t)(k0 + bk) * H2 + h0 + bn4];
        *(float4*)&Bs[bk][bn4] = vb;
        __syncthreads();
#pragma unroll
        for (int k = 0; k < 16; ++k) {
            float4 av = *(const float4*)&As[k][ty * 4];
            float4 bv = *(const float4*)&Bs[k][tx * 4];
            float am[4] = {av.x, av.y, av.z, av.w};
            float bn[4] = {bv.x, bv.y, bv.z, bv.w};
#pragma unroll
            for (int i = 0; i < 4; ++i)
#pragma unroll
                for (int j = 0; j < 4; ++j) acc[i][j] += am[i] * bn[j];
        }
        __syncthreads();
    }
#pragma unroll
    for (int i = 0; i < 4; ++i)
#pragma unroll
        for (int j = 0; j < 4; ++j)
            c2q[((size_t)b * LC + cc0 + ty * 4 + i) * H2 + h0 + tx * 4 + j] = acc[i][j];
}

__global__ void attn_q2c(const float* __restrict__ batt, const float* __restrict__ c_out,
                         float* __restrict__ q2c)
{
    int b = blockIdx.y;
    int h = blockIdx.x * 128 + threadIdx.x;
    const float* C = c_out + (size_t)b * LC * H2;
    const float* w = batt + (size_t)b * LC;
    float acc = 0.f;
    for (int cc = 0; cc < LC; ++cc) acc += w[cc] * C[(size_t)cc * H2 + h];
    q2c[(size_t)b * H2 + h] = acc;
}

__global__ void build_G(const float* __restrict__ c_out, const float* __restrict__ c2q,
                        const float* __restrict__ q2c, float* __restrict__ G)
{
    size_t i = (size_t)blockIdx.x * blockDim.x + threadIdx.x;
    const size_t total = (size_t)BB * LC * (H2 / 4);
    if (i >= total) return;
    int h4 = (int)(i % (H2 / 4));
    size_t r = i / (H2 / 4);
    int b = (int)(r / LC);
    float4 co = ((const float4*)c_out)[r * (H2 / 4) + h4];
    float4 cq = ((const float4*)c2q)[r * (H2 / 4) + h4];
    float4 q2 = ((const float4*)q2c)[(size_t)b * (H2 / 4) + h4];
    float4* Gr = (float4*)(G + r * H8);
    Gr[h4] = make_float4(rtf(co.x), rtf(co.y), rtf(co.z), rtf(co.w));
    Gr[(H2 / 4) + h4] = make_float4(rtf(cq.x), rtf(cq.y), rtf(cq.z), rtf(cq.w));
    Gr[2 * (H2 / 4) + h4] = make_float4(rtf(co.x * cq.x), rtf(co.y * cq.y),
                                        rtf(co.z * cq.z), rtf(co.w * cq.w));
    Gr[3 * (H2 / 4) + h4] = make_float4(rtf(co.x * q2.x), rtf(co.y * q2.y),
                                        rtf(co.z * q2.z), rtf(co.w * q2.w));
}

// ---------------------------------------------------------------------------
extern "C" void kernel_launch(void* const* d_in, const int* in_sizes, int n_in,
                              void* d_out, int out_size)
{
    const int*   q       = (const int*)  d_in[0];
    const int*   c       = (const int*)  d_in[1];
    const float* emb     = (const float*)d_in[2];
    const float* Wih_q   = (const float*)d_in[3];
    const float* Whh_q   = (const float*)d_in[4];
    const float* b_q     = (const float*)d_in[5];
    const float* Wih_c   = (const float*)d_in[6];
    const float* Whh_c   = (const float*)d_in[7];
    const float* b_c     = (const float*)d_in[8];
    const float* Wih_m   = (const float*)d_in[9];
    const float* Whh_m   = (const float*)d_in[10];
    const float* b_m     = (const float*)d_in[11];
    const float* sim_w   = (const float*)d_in[12];
    const float* sim_b   = (const float*)d_in[13];
    const float* start_w = (const float*)d_in[14];
    const float* start_b = (const float*)d_in[15];
    const float* end_w   = (const float*)d_in[16];
    const float* end_b   = (const float*)d_in[17];
    float* out = (float*)d_out;

    float *qemb, *cemb, *xw, *qout, *cout, *S, *smax, *batt, *cw, *qw, *c2q, *q2c, *G, *M, *wcvt;
    cudaGetSymbolAddress((void**)&qemb, g_qemb);
    cudaGetSymbolAddress((void**)&cemb, g_cemb);
    cudaGetSymbolAddress((void**)&xw,   g_xw);
    cudaGetSymbolAddress((void**)&qout, g_qout);
    cudaGetSymbolAddress((void**)&cout, g_cout);
    cudaGetSymbolAddress((void**)&S,    g_S);
    cudaGetSymbolAddress((void**)&smax, g_smax);
    cudaGetSymbolAddress((void**)&batt, g_batt);
    cudaGetSymbolAddress((void**)&cw,   g_cw);
    cudaGetSymbolAddress((void**)&qw,   g_qw);
    cudaGetSymbolAddress((void**)&c2q,  g_c2q);
    cudaGetSymbolAddress((void**)&q2c,  g_q2c);
    cudaGetSymbolAddress((void**)&G,    g_G);
    cudaGetSymbolAddress((void**)&M,    g_M);
    cudaGetSymbolAddress((void**)&wcvt, g_wcvt);

    const int lstm_smem = (HH * BB + 16 * HH + 64 * 16) * (int)sizeof(float);
    cudaFuncSetAttribute(lstm_scan, cudaFuncAttributeMaxDynamicSharedMemorySize, lstm_smem);
    cudaFuncSetAttribute(gemm_tf32, cudaFuncAttributeMaxDynamicSharedMemorySize, GEMM_SMEM);

    gather_emb<<<(BB * LQ * EE + 255) / 256, 256>>>(q, emb, qemb, BB * LQ * EE);
    gather_emb<<<(BB * LC * EE + 255) / 256, 256>>>(c, emb, cemb, BB * LC * EE);

    // q BiLSTM
    cvt_tf32<<<(2 * G4 * EE + 255) / 256, 256>>>(Wih_q, wcvt, 2 * G4 * EE);
    for (int d = 0; d < 2; ++d)
        gemm_tf32<<<dim3(G4 / 128, (BB * LQ) / 128), 128, GEMM_SMEM>>>(
            qemb, wcvt + (size_t)d * G4 * EE, b_q + (size_t)d * G4,
            xw + (size_t)d * BB * LQ * G4, BB * LQ, G4, EE);
    lstm_scan<<<128, 256, lstm_smem>>>(xw, Whh_q, qout, LQ);

    // c BiLSTM
    cvt_tf32<<<(2 * G4 * EE + 255) / 256, 256>>>(Wih_c, wcvt, 2 * G4 * EE);
    for (int d = 0; d < 2; ++d)
        gemm_tf32<<<dim3(G4 / 128, (BB * LC) / 128), 128, GEMM_SMEM>>>(
            cemb, wcvt + (size_t)d * G4 * EE, b_c + (size_t)d * G4,
            xw + (size_t)d * BB * LC * G4, BB * LC, G4, EE);
    lstm_scan<<<128, 256, lstm_smem>>>(xw, Whh_c, cout, LC);

    // attention
    rowdot<<<(BB * LC) / 8, 256>>>(cout, sim_w, nullptr, cw, BB * LC);
    rowdot<<<(BB * LQ) / 8, 256>>>(qout, sim_w + H2, nullptr, qw, BB * LQ);
    attn_S<<<dim3(LC / 64, BB), 256>>>(cout, qout, sim_w, sim_b, cw, qw, S);
    softmax64<<<(BB * LC) / 8, 256>>>(S, smax, BB * LC);
    softmax512<<<BB, 512>>>(smax, batt);
    attn_c2q<<<dim3(H2 / 64, LC / 64, BB), 256>>>(S, qout, c2q);
    attn_q2c<<<dim3(H2 / 128, BB), 128>>>(batt, cout, q2c);
    build_G<<<(int)(((size_t)BB * LC * (H2 / 4) + 255) / 256), 256>>>(cout, c2q, q2c, G);

    // modeling BiLSTM
    cvt_tf32<<<(2 * G4 * H8 + 255) / 256, 256>>>(Wih_m, wcvt, 2 * G4 * H8);
    for (int d = 0; d < 2; ++d)
        gemm_tf32<<<dim3(G4 / 128, (BB * LC) / 128), 128, GEMM_SMEM>>>(
            G, wcvt + (size_t)d * G4 * H8, b_m + (size_t)d * G4,
            xw + (size_t)d * BB * LC * G4, BB * LC, G4, H8);
    lstm_scan<<<128, 256, lstm_smem>>>(xw, Whh_m, M, LC);

    rowdot<<<(BB * LC) / 8, 256>>>(M, start_w, start_b, out, BB * LC);
    rowdot<<<(BB * LC) / 8, 256>>>(M, end_w, end_b, out + (size_t)BB * LC, BB * LC);
}